// round 1
// baseline (speedup 1.0000x reference)
#include <cuda_runtime.h>

// Reference math collapses: s = exp(y - y) == 1 (y finite), out = sigmoid(2*1).
// Entire 16x64x128x128 fp32 output is the constant sigmoid(2.0).
// Optimal kernel = 64 MiB constant fill -> pure HBM-write roofline.

__global__ void fill_sigmoid2_vec4(float4* __restrict__ out4, int n4) {
    int i = blockIdx.x * blockDim.x + threadIdx.x;
    if (i < n4) {
        const float v = 0.8807970779778823f; // sigmoid(2.0)
        out4[i] = make_float4(v, v, v, v);
    }
}

__global__ void fill_sigmoid2_tail(float* __restrict__ out, int start, int n) {
    int i = start + blockIdx.x * blockDim.x + threadIdx.x;
    if (i < n) out[i] = 0.8807970779778823f;
}

extern "C" void kernel_launch(void* const* d_in, const int* in_sizes, int n_in,
                              void* d_out, int out_size) {
    (void)d_in; (void)in_sizes; (void)n_in;
    float* out = (float*)d_out;
    int n4 = out_size / 4;          // 16,777,216 / 4 = 4,194,304
    int tail = out_size - n4 * 4;   // 0 for this problem

    if (n4 > 0) {
        int threads = 256;
        int blocks = (n4 + threads - 1) / threads;   // 16384 blocks
        fill_sigmoid2_vec4<<<blocks, threads>>>((float4*)out, n4);
    }
    if (tail > 0) {
        fill_sigmoid2_tail<<<1, 32>>>(out, n4 * 4, out_size);
    }
}

// round 3
// speedup vs baseline: 1.0718x; 1.0718x over previous
#include <cuda_runtime.h>

// Output is the constant sigmoid(2.0) everywhere (s = exp(y-y) == 1).
// 64 MiB constant fill. Output fits in L2 (126 MB) -> bound by L2 write
// throughput (~6300 B/cyc chip-wide), not HBM. Strategy: 8 independent
// STG.128 per thread, warp-coalesced, exact-cover grid, 32-bit index math
// on the fast path.

#ifndef VEC_PER_THREAD
#define VEC_PER_THREAD 8   // 8 x float4 = 128 B per thread
#endif

__global__ void __launch_bounds__(256) fill_sigmoid2_v8(float4* __restrict__ out4) {
    const float v = 0.8807970779778823f; // sigmoid(2.0)
    const float4 val = make_float4(v, v, v, v);
    // Block covers 256*8 = 2048 consecutive float4s (32 KB), strided so each
    // STG.128 is a contiguous 4KB warp transaction. Max index = 4,194,304
    // float4s -> fits in 32-bit; ptxas keeps address math to 1 IMAD/store.
    unsigned base = blockIdx.x * (256u * VEC_PER_THREAD) + threadIdx.x;
#pragma unroll
    for (int k = 0; k < VEC_PER_THREAD; k++) {
        out4[base + (unsigned)k * 256u] = val;
    }
}

__global__ void fill_sigmoid2_tail(float* __restrict__ out, int start, int n) {
    int i = start + blockIdx.x * blockDim.x + threadIdx.x;
    if (i < n) out[i] = 0.8807970779778823f;
}

extern "C" void kernel_launch(void* const* d_in, const int* in_sizes, int n_in,
                              void* d_out, int out_size) {
    (void)d_in; (void)in_sizes; (void)n_in;
    float* out = (float*)d_out;

    const int threads = 256;
    const int f4_per_block = threads * VEC_PER_THREAD;        // 2048 float4 = 32 KB
    int n4 = out_size / 4;                                    // 4,194,304
    int blocks = n4 / f4_per_block;                           // 2048 exact
    int covered4 = blocks * f4_per_block;

    if (blocks > 0) {
        fill_sigmoid2_v8<<<blocks, threads>>>((float4*)out);
    }
    // Remainder (0 for this shape, kept for generality)
    int rem_elems = out_size - covered4 * 4;
    if (rem_elems > 0) {
        int t = 256;
        int b = (rem_elems + t - 1) / t;
        fill_sigmoid2_tail<<<b, t>>>(out, covered4 * 4, out_size);
    }
}